// round 8
// baseline (speedup 1.0000x reference)
#include <cuda_runtime.h>
#include <cuda_bf16.h>
#include <cstdint>

#define B 4
#define L 512
#define D 128
#define QT 16            // queries per block
#define EPSV 1e-8f

typedef unsigned long long ull;

// ---- smem carve (float offsets) ----
#define OFF_WTS 0              // [128][128]
#define OFF_WXS 16384          // [128][128]
#define OFF_XST 32768          // [128][40]  x by virtual-row slot
#define OFF_XS  37888          // [18][128]  row-major X tile
#define OFF_QKS 40192          // [18][128]  k rows
#define OFF_QQS 42496          // [16][128]  q rows
#define SMEM_FLOATS 44544
#define SMEM_BYTES (SMEM_FLOATS * 4)

__device__ __forceinline__ void cp_async16(void* dst, const void* src) {
    unsigned int s = (unsigned int)__cvta_generic_to_shared(dst);
    asm volatile("cp.async.ca.shared.global [%0], [%1], 16;" :: "r"(s), "l"(src));
}
__device__ __forceinline__ void cp_commit() {
    asm volatile("cp.async.commit_group;");
}
template<int N>
__device__ __forceinline__ void cp_wait() {
    asm volatile("cp.async.wait_group %0;" :: "n"(N));
}

__device__ __forceinline__ ull ffma2(ull a, ull b, ull c) {
    ull d;
    asm("fma.rn.f32x2 %0, %1, %2, %3;" : "=l"(d) : "l"(a), "l"(b), "l"(c));
    return d;
}
__device__ __forceinline__ ull dup2(float x) {
    ull d;
    unsigned int u = __float_as_uint(x);
    asm("mov.b64 %0, {%1, %1};" : "=l"(d) : "r"(u));
    return d;
}

// accurate tanh: 1 - 2/(e^{2x}+1)
__device__ __forceinline__ float tanh_acc(float x) {
    float e2 = __expf(2.0f * x);
    return 1.0f - __fdividef(2.0f, e2 + 1.0f);
}

// ---------------------------------------------------------------------------
// Fully fused, all-warp GEMM.
// Virtual rows: 0..15 = q rows (X[q0..q0+15] @ Wt), 16..33 = k tile rows
// (X[q0-1..q0+16] @ Wx), 34..39 junk (zero x).
// 20 warp-units of 8 rows x 32 cols; lane = 8 rows x 1 col, row-paired f32x2.
// grid: (L/QT, B) = (32, 4) = 128 blocks; 512 threads.
// ---------------------------------------------------------------------------
__global__ __launch_bounds__(512, 1) void fused_kernel(
    const float* __restrict__ X,  const float* __restrict__ Wt,
    const float* __restrict__ Wx, const float* __restrict__ Wa,
    const float* __restrict__ bh, const float* __restrict__ ba_p,
    float* __restrict__ out)
{
    extern __shared__ float sm[];
    float* Wts = sm + OFF_WTS;
    float* Wxs = sm + OFF_WXS;
    float* XsT = sm + OFF_XST;   // [d][40]
    float* Xs  = sm + OFF_XS;    // [r][128], tile rows 0..17 = X[q0-1 .. q0+16]
    float* qks = sm + OFF_QKS;
    float* qqs = sm + OFF_QQS;

    const int b    = blockIdx.y;
    const int q0   = blockIdx.x * QT;
    const int tid  = threadIdx.x;
    const int wid  = tid >> 5;
    const int lane = tid & 31;
    const float* XB = X + b * L * D;

    // ---- stage weights: group0 = d<64 of both, group1 = d>=64 ----
    {
        const float4* Wt4 = (const float4*)Wt;
        const float4* Wx4 = (const float4*)Wx;
        #pragma unroll
        for (int j = 0; j < 4; j++) {
            int idx = j * 512 + tid;               // 0..2047 (= d<64)
            cp_async16(Wts + idx * 4, Wt4 + idx);
            cp_async16(Wxs + idx * 4, Wx4 + idx);
        }
        cp_commit();
        #pragma unroll
        for (int j = 0; j < 4; j++) {
            int idx = 2048 + j * 512 + tid;        // d>=64
            cp_async16(Wts + idx * 4, Wt4 + idx);
            cp_async16(Wxs + idx * 4, Wx4 + idx);
        }
        cp_commit();
    }

    // ---- zero junk slots 34..39 of XsT ----
    for (int i = tid; i < 128 * 6; i += 512)
        XsT[(i / 6) * 40 + 34 + (i % 6)] = 0.f;

    // ---- X tile: 18 rows (q0-1 .. q0+16 clamped); row-major + slotted ----
    for (int i = tid; i < 18 * 32; i += 512) {
        int r  = i >> 5;           // tile row 0..17
        int d4 = i & 31;
        int row = min(max(q0 - 1 + r, 0), L - 1);
        float4 v = ((const float4*)(XB + row * D))[d4];
        ((float4*)(Xs + r * D))[d4] = v;
        int d0 = d4 * 4;
        // k-section slot (always)
        XsT[(d0 + 0) * 40 + 16 + r] = v.x;
        XsT[(d0 + 1) * 40 + 16 + r] = v.y;
        XsT[(d0 + 2) * 40 + 16 + r] = v.z;
        XsT[(d0 + 3) * 40 + 16 + r] = v.w;
        // q-section slot (tile rows 1..16 -> slots 0..15)
        if (r >= 1 && r <= 16) {
            XsT[(d0 + 0) * 40 + (r - 1)] = v.x;
            XsT[(d0 + 1) * 40 + (r - 1)] = v.y;
            XsT[(d0 + 2) * 40 + (r - 1)] = v.z;
            XsT[(d0 + 3) * 40 + (r - 1)] = v.w;
        }
    }

    // ---- GEMM: units u = wid and wid+16 (if < 20) ----
    const int u1 = wid;
    const int u2 = wid + 16;
    const bool has2 = (u2 < 20);

    const int rg1 = u1 >> 2, cq1 = u1 & 3;
    const int v01 = rg1 * 8;
    const int col1 = cq1 * 32 + lane;
    const float* W1 = ((v01 < 16) ? Wts : Wxs) + col1;
    const float* xb1 = XsT + v01;

    const int rg2 = 4, cq2 = u2 & 3;            // units 16..19 are rowgroup 4
    const int v02 = rg2 * 8;
    const int col2 = cq2 * 32 + lane;
    const float* W2 = Wxs + col2;
    const float* xb2 = XsT + v02;

    ull acc1[4] = {0,0,0,0};
    ull acc2[4] = {0,0,0,0};

    cp_wait<1>();
    __syncthreads();

    #pragma unroll 8
    for (int d = 0; d < 64; d++) {
        {
            ull wd = dup2(W1[d * D]);
            ulonglong2 xa = *(const ulonglong2*)(xb1 + d * 40);
            ulonglong2 xc = *(const ulonglong2*)(xb1 + d * 40 + 4);
            acc1[0] = ffma2(xa.x, wd, acc1[0]);
            acc1[1] = ffma2(xa.y, wd, acc1[1]);
            acc1[2] = ffma2(xc.x, wd, acc1[2]);
            acc1[3] = ffma2(xc.y, wd, acc1[3]);
        }
        if (has2) {
            ull wd = dup2(W2[d * D]);
            ulonglong2 xa = *(const ulonglong2*)(xb2 + d * 40);
            ulonglong2 xc = *(const ulonglong2*)(xb2 + d * 40 + 4);
            acc2[0] = ffma2(xa.x, wd, acc2[0]);
            acc2[1] = ffma2(xa.y, wd, acc2[1]);
            acc2[2] = ffma2(xc.x, wd, acc2[2]);
            acc2[3] = ffma2(xc.y, wd, acc2[3]);
        }
    }

    cp_wait<0>();
    __syncthreads();

    #pragma unroll 8
    for (int d = 64; d < 128; d++) {
        {
            ull wd = dup2(W1[d * D]);
            ulonglong2 xa = *(const ulonglong2*)(xb1 + d * 40);
            ulonglong2 xc = *(const ulonglong2*)(xb1 + d * 40 + 4);
            acc1[0] = ffma2(xa.x, wd, acc1[0]);
            acc1[1] = ffma2(xa.y, wd, acc1[1]);
            acc1[2] = ffma2(xc.x, wd, acc1[2]);
            acc1[3] = ffma2(xc.y, wd, acc1[3]);
        }
        if (has2) {
            ull wd = dup2(W2[d * D]);
            ulonglong2 xa = *(const ulonglong2*)(xb2 + d * 40);
            ulonglong2 xc = *(const ulonglong2*)(xb2 + d * 40 + 4);
            acc2[0] = ffma2(xa.x, wd, acc2[0]);
            acc2[1] = ffma2(xa.y, wd, acc2[1]);
            acc2[2] = ffma2(xc.x, wd, acc2[2]);
            acc2[3] = ffma2(xc.y, wd, acc2[3]);
        }
    }

    // ---- store unit results ----
    {
        #pragma unroll
        for (int j = 0; j < 4; j++) {
            float2 f = *(float2*)&acc1[j];
            int r0 = v01 + 2 * j;
            if (v01 < 16) {
                qqs[(r0    ) * D + col1] = f.x;
                qqs[(r0 + 1) * D + col1] = f.y;
            } else {
                int kr = r0 - 16;
                if (kr < 18)     qks[(kr    ) * D + col1] = f.x;
                if (kr + 1 < 18) qks[(kr + 1) * D + col1] = f.y;
            }
        }
        if (has2) {
            #pragma unroll
            for (int j = 0; j < 4; j++) {
                float2 f = *(float2*)&acc2[j];
                int kr = v02 - 16 + 2 * j;
                if (kr < 18)     qks[(kr    ) * D + col2] = f.x;
                if (kr + 1 < 18) qks[(kr + 1) * D + col2] = f.y;
            }
        }
    }
    __syncthreads();

    // ---- window phase: 16 warps, warp == query ----
    const int rq = wid;               // 0..15
    const int qi = q0 + rq;

    float4 qv  = ((const float4*)(qqs + rq * D))[lane];
    float4 bhv = ((const float4*)bh)[lane];
    qv.x += bhv.x; qv.y += bhv.y; qv.z += bhv.z; qv.w += bhv.w;
    const float4 wv = ((const float4*)Wa)[lane];
    const float bav = ba_p[0];

    float e[3];
    #pragma unroll
    for (int tt = 0; tt < 3; tt++) {
        int j = qi - 1 + tt;                       // global key, tile row rq+tt
        float4 kv = ((const float4*)(qks + (rq + tt) * D))[lane];
        float p = tanh_acc(qv.x + kv.x) * wv.x
                + tanh_acc(qv.y + kv.y) * wv.y
                + tanh_acc(qv.z + kv.z) * wv.z
                + tanh_acc(qv.w + kv.w) * wv.w;
        #pragma unroll
        for (int o = 16; o > 0; o >>= 1)
            p += __shfl_xor_sync(0xffffffffu, p, o);
        e[tt] = (j >= 0 && j < L) ? (p + bav) : -1e30f;
    }

    float m  = fmaxf(e[0], fmaxf(e[1], e[2]));
    float w0 = __expf(e[0] - m);
    float w1 = __expf(e[1] - m);
    float w2 = __expf(e[2] - m);
    float inv = __fdividef(1.0f, w0 + w1 + w2 + EPSV);

    float4 o4 = make_float4(0.f, 0.f, 0.f, 0.f);
    #pragma unroll
    for (int tt = 0; tt < 3; tt++) {
        float w = (tt == 0) ? w0 : (tt == 1) ? w1 : w2;
        float a = w * inv;
        float4 xv = ((const float4*)(Xs + (rq + tt) * D))[lane];
        o4.x = fmaf(a, xv.x, o4.x);
        o4.y = fmaf(a, xv.y, o4.y);
        o4.z = fmaf(a, xv.z, o4.z);
        o4.w = fmaf(a, xv.w, o4.w);
    }
    ((float4*)(out + (b * L + qi) * D))[lane] = o4;
}

extern "C" void kernel_launch(void* const* d_in, const int* in_sizes, int n_in,
                              void* d_out, int out_size)
{
    const float* X  = (const float*)d_in[0];
    const float* Wt = (const float*)d_in[1];
    const float* Wx = (const float*)d_in[2];
    const float* Wa = (const float*)d_in[3];
    const float* bh = (const float*)d_in[4];
    const float* ba = (const float*)d_in[5];
    float* out = (float*)d_out;

    cudaFuncSetAttribute(fused_kernel,
                         cudaFuncAttributeMaxDynamicSharedMemorySize, SMEM_BYTES);
    dim3 grid(L / QT, B);
    fused_kernel<<<grid, 512, SMEM_BYTES>>>(X, Wt, Wx, Wa, bh, ba, out);
}

// round 9
// speedup vs baseline: 1.1380x; 1.1380x over previous
#include <cuda_runtime.h>
#include <cuda_bf16.h>
#include <cstdint>

#define B 4
#define L 512
#define D 128
#define QT 16            // queries per block
#define EPSV 1e-8f

typedef unsigned long long ull;

// ---- smem carve (float offsets) ----
// Virtual-row slots in XsT (pair-packed for f32x2):
//   0..15  : q rows   (global q0+r      @ Wt)
//   16..31 : k rows   (global q0+r-16   @ Wx)   [interior]
//   32     : k halo   (global q0-1      @ Wx)
//   33     : k halo   (global q0+16     @ Wx)
#define OFF_WTS 0              // [128][128]
#define OFF_WXS 16384          // [128][128]
#define OFF_XST 32768          // [128][36]
#define OFF_XS  37376          // [18][128] row-major X tile (rows q0-1..q0+16)
#define OFF_QKS 39680          // [18][128] k rows (tile rows 0..17)
#define OFF_QQS 41984          // [16][128] q rows
#define SMEM_FLOATS 44032
#define SMEM_BYTES (SMEM_FLOATS * 4)

__device__ __forceinline__ void cp_async16(void* dst, const void* src) {
    unsigned int s = (unsigned int)__cvta_generic_to_shared(dst);
    asm volatile("cp.async.ca.shared.global [%0], [%1], 16;" :: "r"(s), "l"(src));
}
__device__ __forceinline__ void cp_commit() {
    asm volatile("cp.async.commit_group;");
}
template<int N>
__device__ __forceinline__ void cp_wait() {
    asm volatile("cp.async.wait_group %0;" :: "n"(N));
}

__device__ __forceinline__ ull ffma2(ull a, ull b, ull c) {
    ull d;
    asm("fma.rn.f32x2 %0, %1, %2, %3;" : "=l"(d) : "l"(a), "l"(b), "l"(c));
    return d;
}
__device__ __forceinline__ ull dup2(float x) {
    ull d;
    unsigned int u = __float_as_uint(x);
    asm("mov.b64 %0, {%1, %1};" : "=l"(d) : "r"(u));
    return d;
}

// accurate tanh: 1 - 2/(e^{2x}+1)
__device__ __forceinline__ float tanh_acc(float x) {
    float e2 = __expf(2.0f * x);
    return 1.0f - __fdividef(2.0f, e2 + 1.0f);
}

// ---------------------------------------------------------------------------
// grid: (L/QT, B) = (32, 4) = 128 blocks; 512 threads.
// 16 warps = 4 rowgroups x 4 colgroups; rowgroup 3 carries the 2 halo rows.
// ---------------------------------------------------------------------------
__global__ __launch_bounds__(512, 1) void fused_kernel(
    const float* __restrict__ X,  const float* __restrict__ Wt,
    const float* __restrict__ Wx, const float* __restrict__ Wa,
    const float* __restrict__ bh, const float* __restrict__ ba_p,
    float* __restrict__ out)
{
    extern __shared__ float sm[];
    float* Wts = sm + OFF_WTS;
    float* Wxs = sm + OFF_WXS;
    float* XsT = sm + OFF_XST;   // [d][36]
    float* Xs  = sm + OFF_XS;
    float* qks = sm + OFF_QKS;
    float* qqs = sm + OFF_QQS;

    const int b    = blockIdx.y;
    const int q0   = blockIdx.x * QT;
    const int tid  = threadIdx.x;
    const int wid  = tid >> 5;
    const int lane = tid & 31;
    const int g    = wid >> 2;     // rowgroup 0..3
    const int cgrp = wid & 3;      // colgroup 0..3
    const float* XB = X + b * L * D;

    // ---- stage weights: group0 = d<64 of both, group1 = d>=64 ----
    {
        const float4* Wt4 = (const float4*)Wt;
        const float4* Wx4 = (const float4*)Wx;
        #pragma unroll
        for (int j = 0; j < 4; j++) {
            int idx = j * 512 + tid;               // d < 64
            cp_async16(Wts + idx * 4, Wt4 + idx);
            cp_async16(Wxs + idx * 4, Wx4 + idx);
        }
        cp_commit();
        #pragma unroll
        for (int j = 0; j < 4; j++) {
            int idx = 2048 + j * 512 + tid;        // d >= 64
            cp_async16(Wts + idx * 4, Wt4 + idx);
            cp_async16(Wxs + idx * 4, Wx4 + idx);
        }
        cp_commit();
    }

    // ---- X tile: 18 rows (q0-1 .. q0+16 clamped); row-major + slotted ----
    for (int i = tid; i < 18 * 32; i += 512) {
        int r  = i >> 5;           // tile row 0..17
        int d4 = i & 31;
        int row = min(max(q0 - 1 + r, 0), L - 1);
        float4 v = ((const float4*)(XB + row * D))[d4];
        ((float4*)(Xs + r * D))[d4] = v;
        int d0 = d4 * 4;
        int ks = (r == 0) ? 32 : (r == 17) ? 33 : (15 + r);   // k slot
        XsT[(d0 + 0) * 36 + ks] = v.x;
        XsT[(d0 + 1) * 36 + ks] = v.y;
        XsT[(d0 + 2) * 36 + ks] = v.z;
        XsT[(d0 + 3) * 36 + ks] = v.w;
        if (r >= 1 && r <= 16) {                               // q slot
            int qsl = r - 1;
            XsT[(d0 + 0) * 36 + qsl] = v.x;
            XsT[(d0 + 1) * 36 + qsl] = v.y;
            XsT[(d0 + 2) * 36 + qsl] = v.z;
            XsT[(d0 + 3) * 36 + qsl] = v.w;
        }
    }

    // ---- GEMM ----
    const int col = cgrp * 32 + lane;
    const float* Wp = ((g < 2) ? Wts : Wxs) + col;
    const float* xp = XsT + ((g < 3) ? g * 8 : 24);

    ull acc[5] = {0, 0, 0, 0, 0};

    cp_wait<1>();
    __syncthreads();

    if (g < 3) {
        #pragma unroll 8
        for (int d = 0; d < 64; d++) {
            ull wd = dup2(Wp[d * D]);
            const float* xr = xp + d * 36;
            ulonglong2 xa = *(const ulonglong2*)xr;
            ulonglong2 xb = *(const ulonglong2*)(xr + 4);
            acc[0] = ffma2(xa.x, wd, acc[0]);
            acc[1] = ffma2(xa.y, wd, acc[1]);
            acc[2] = ffma2(xb.x, wd, acc[2]);
            acc[3] = ffma2(xb.y, wd, acc[3]);
        }
    } else {
        #pragma unroll 8
        for (int d = 0; d < 64; d++) {
            ull wd = dup2(Wp[d * D]);
            const float* xr = xp + d * 36;
            ulonglong2 xa = *(const ulonglong2*)xr;
            ulonglong2 xb = *(const ulonglong2*)(xr + 4);
            ull xc = *(const ull*)(xr + 8);
            acc[0] = ffma2(xa.x, wd, acc[0]);
            acc[1] = ffma2(xa.y, wd, acc[1]);
            acc[2] = ffma2(xb.x, wd, acc[2]);
            acc[3] = ffma2(xb.y, wd, acc[3]);
            acc[4] = ffma2(xc,   wd, acc[4]);
        }
    }

    cp_wait<0>();
    __syncthreads();

    if (g < 3) {
        #pragma unroll 8
        for (int d = 64; d < 128; d++) {
            ull wd = dup2(Wp[d * D]);
            const float* xr = xp + d * 36;
            ulonglong2 xa = *(const ulonglong2*)xr;
            ulonglong2 xb = *(const ulonglong2*)(xr + 4);
            acc[0] = ffma2(xa.x, wd, acc[0]);
            acc[1] = ffma2(xa.y, wd, acc[1]);
            acc[2] = ffma2(xb.x, wd, acc[2]);
            acc[3] = ffma2(xb.y, wd, acc[3]);
        }
    } else {
        #pragma unroll 8
        for (int d = 64; d < 128; d++) {
            ull wd = dup2(Wp[d * D]);
            const float* xr = xp + d * 36;
            ulonglong2 xa = *(const ulonglong2*)xr;
            ulonglong2 xb = *(const ulonglong2*)(xr + 4);
            ull xc = *(const ull*)(xr + 8);
            acc[0] = ffma2(xa.x, wd, acc[0]);
            acc[1] = ffma2(xa.y, wd, acc[1]);
            acc[2] = ffma2(xb.x, wd, acc[2]);
            acc[3] = ffma2(xb.y, wd, acc[3]);
            acc[4] = ffma2(xc,   wd, acc[4]);
        }
    }

    // ---- store unit results (slot -> qqs/qks) ----
    {
        const int s0 = (g < 3) ? g * 8 : 24;
        const int nu = (g < 3) ? 4 : 5;
        #pragma unroll
        for (int j = 0; j < 5; j++) {
            if (j >= nu) break;
            float2 f = *(float2*)&acc[j];
            int s = s0 + 2 * j;
            #pragma unroll
            for (int h = 0; h < 2; h++) {
                int slot = s + h;
                float v = h ? f.y : f.x;
                if (slot < 16)       qqs[slot * D + col] = v;
                else if (slot < 32)  qks[(slot - 15) * D + col] = v;
                else if (slot == 32) qks[0 * D + col]  = v;
                else                 qks[17 * D + col] = v;
            }
        }
    }
    __syncthreads();

    // ---- window phase: 16 warps, warp == query ----
    const int rq = wid;               // 0..15
    const int qi = q0 + rq;

    float4 qv  = ((const float4*)(qqs + rq * D))[lane];
    float4 bhv = ((const float4*)bh)[lane];
    qv.x += bhv.x; qv.y += bhv.y; qv.z += bhv.z; qv.w += bhv.w;
    const float4 wv = ((const float4*)Wa)[lane];
    const float bav = ba_p[0];

    float e[3];
    #pragma unroll
    for (int tt = 0; tt < 3; tt++) {
        int j = qi - 1 + tt;                       // global key, tile row rq+tt
        float4 kv = ((const float4*)(qks + (rq + tt) * D))[lane];
        float p = tanh_acc(qv.x + kv.x) * wv.x
                + tanh_acc(qv.y + kv.y) * wv.y
                + tanh_acc(qv.z + kv.z) * wv.z
                + tanh_acc(qv.w + kv.w) * wv.w;
        #pragma unroll
        for (int o = 16; o > 0; o >>= 1)
            p += __shfl_xor_sync(0xffffffffu, p, o);
        e[tt] = (j >= 0 && j < L) ? (p + bav) : -1e30f;
    }

    float m  = fmaxf(e[0], fmaxf(e[1], e[2]));
    float w0 = __expf(e[0] - m);
    float w1 = __expf(e[1] - m);
    float w2 = __expf(e[2] - m);
    float inv = __fdividef(1.0f, w0 + w1 + w2 + EPSV);

    float4 o4 = make_float4(0.f, 0.f, 0.f, 0.f);
    #pragma unroll
    for (int tt = 0; tt < 3; tt++) {
        float w = (tt == 0) ? w0 : (tt == 1) ? w1 : w2;
        float a = w * inv;
        float4 xv = ((const float4*)(Xs + (rq + tt) * D))[lane];
        o4.x = fmaf(a, xv.x, o4.x);
        o4.y = fmaf(a, xv.y, o4.y);
        o4.z = fmaf(a, xv.z, o4.z);
        o4.w = fmaf(a, xv.w, o4.w);
    }
    ((float4*)(out + (b * L + qi) * D))[lane] = o4;
}

extern "C" void kernel_launch(void* const* d_in, const int* in_sizes, int n_in,
                              void* d_out, int out_size)
{
    const float* X  = (const float*)d_in[0];
    const float* Wt = (const float*)d_in[1];
    const float* Wx = (const float*)d_in[2];
    const float* Wa = (const float*)d_in[3];
    const float* bh = (const float*)d_in[4];
    const float* ba = (const float*)d_in[5];
    float* out = (float*)d_out;

    cudaFuncSetAttribute(fused_kernel,
                         cudaFuncAttributeMaxDynamicSharedMemorySize, SMEM_BYTES);
    dim3 grid(L / QT, B);
    fused_kernel<<<grid, 512, SMEM_BYTES>>>(X, Wt, Wx, Wa, bh, ba, out);
}